// round 12
// baseline (speedup 1.0000x reference)
#include <cuda_runtime.h>
#include <stdint.h>
#include <math.h>

#define BV 16
#define CV 128
#define HV 128
#define WV 128

#define A_T8 16384             // int8 A tile per term: [ks 4][mt 8][lane 32][16B]
#define NPXI 66                // 64 px + 2 halo
#define B_T8 (4 * NPXI * 32)   // 8448 B per term

__device__ float g_smax[BV];
__device__ float g_wmax[CV];
__device__ float g_sw[BV * CV];          // per (b, oc) weight scale
__device__ unsigned int g_xmax_bits;     // global max|x| as uint bits
// int8 A tiles: [b][tap 0..8][term 0..1], each 16KB, IMMA-fragment packed
__device__ unsigned char g_wa8[(size_t)BV * 9 * 2 * A_T8];

// ---------------- helpers ----------------
__device__ __forceinline__ uint32_t smem_u32(const void* p) {
    uint32_t a;
    asm("{ .reg .u64 t; cvta.to.shared.u64 t, %1; cvt.u32.u64 %0, t; }" : "=r"(a) : "l"(p));
    return a;
}
// int8 A fragment address (mma.m16n8k32 row-major A)
__device__ __forceinline__ uint32_t addrA8(int o, int ic) {
    int ks = ic >> 5, kk = ic & 31, mt = o >> 4;
    int lane = ((o & 7) << 2) | ((kk & 15) >> 2);
    int reg = ((kk >> 4) << 1) | ((o >> 3) & 1);
    return (uint32_t)(((ks * 8 + mt) * 32 + lane) * 16 + reg * 4 + (kk & 3));
}
__device__ __forceinline__ void imma(int* c, const uint32_t* a, const uint32_t* b2) {
    asm volatile(
        "mma.sync.aligned.m16n8k32.row.col.s32.s8.s8.s32 "
        "{%0,%1,%2,%3}, {%4,%5,%6,%7}, {%8,%9}, {%0,%1,%2,%3};"
        : "+r"(c[0]), "+r"(c[1]), "+r"(c[2]), "+r"(c[3])
        : "r"(a[0]), "r"(a[1]), "r"(a[2]), "r"(a[3]), "r"(b2[0]), "r"(b2[1]));
}

// ---------------- Kernel 1: per-sample style inf-norm (+ reset xmax) ----------------
__global__ void k_smax(const float* __restrict__ style) {
    if (blockIdx.x == 0 && threadIdx.x == 0) g_xmax_bits = 0u;
    int b = blockIdx.x, t = threadIdx.x;
    float m = 0.f;
    for (int i = t; i < CV; i += 32) m = fmaxf(m, fabsf(style[b * CV + i]));
    #pragma unroll
    for (int o = 16; o; o >>= 1) m = fmaxf(m, __shfl_xor_sync(0xffffffffu, m, o));
    if (t == 0) g_smax[b] = m;
}

// ---------------- Kernel 1b: global max|x| ----------------
__global__ void k_xmax(const float* __restrict__ x, int n) {
    float m = 0.f;
    for (size_t i = (size_t)blockIdx.x * 256 + threadIdx.x; i < (size_t)n; i += (size_t)gridDim.x * 256)
        m = fmaxf(m, fabsf(x[i]));
    #pragma unroll
    for (int o = 16; o; o >>= 1) m = fmaxf(m, __shfl_xor_sync(0xffffffffu, m, o));
    __shared__ float red[8];
    int t = threadIdx.x;
    if ((t & 31) == 0) red[t >> 5] = m;
    __syncthreads();
    if (t == 0) {
        float mm = 0.f;
        #pragma unroll
        for (int i = 0; i < 8; i++) mm = fmaxf(mm, red[i]);
        atomicMax(&g_xmax_bits, __float_as_uint(mm));
    }
}

// ---------------- Kernel 2: per-out-channel weight inf-norm ----------------
__global__ void k_wmax(const float* __restrict__ weight) {
    int o = blockIdx.x, t = threadIdx.x;
    const float* wp = weight + (size_t)o * CV * 9;
    float m = 0.f;
    for (int i = t; i < CV * 9; i += 128) m = fmaxf(m, fabsf(wp[i]));
    __shared__ float red[4];
    #pragma unroll
    for (int off = 16; off; off >>= 1) m = fmaxf(m, __shfl_xor_sync(0xffffffffu, m, off));
    if ((t & 31) == 0) red[t >> 5] = m;
    __syncthreads();
    if (t == 0) g_wmax[o] = fmaxf(fmaxf(red[0], red[1]), fmaxf(red[2], red[3]));
}

// ---------------- Kernel 3: modulate+demodulate -> int8 2-term A tiles ----------------
__global__ void k_mod(const float* __restrict__ style, const float* __restrict__ weight) {
    int o = blockIdx.x, b = blockIdx.y, i = threadIdx.x;
    float s = style[b * CV + i] / g_smax[b];
    float scale = (1.0f / sqrtf((float)(CV * 9))) / g_wmax[o] * s;
    const float* wp = weight + ((size_t)o * CV + i) * 9;
    float v[9];
    float ss = 0.f, mv = 0.f;
    #pragma unroll
    for (int k = 0; k < 9; k++) {
        v[k] = wp[k] * scale;
        ss += v[k] * v[k];
        mv = fmaxf(mv, fabsf(v[k]));
    }
    __shared__ float reds[4], redm[4];
    #pragma unroll
    for (int off = 16; off; off >>= 1) {
        ss += __shfl_xor_sync(0xffffffffu, ss, off);
        mv = fmaxf(mv, __shfl_xor_sync(0xffffffffu, mv, off));
    }
    if ((i & 31) == 0) { reds[i >> 5] = ss; redm[i >> 5] = mv; }
    __syncthreads();
    float coe = rsqrtf(reds[0] + reds[1] + reds[2] + reds[3] + 1e-8f);
    float mvmax = fmaxf(fmaxf(redm[0], redm[1]), fmaxf(redm[2], redm[3]));
    mvmax = fmaxf(mvmax, 1e-30f);
    if (i == 0) g_sw[b * CV + o] = coe * mvmax * (1.0f / 126.0f);
    float invq = 126.0f / mvmax;   // quantization of v[k] (coe cancels)
    uint32_t off = addrA8(o, i);
    #pragma unroll
    for (int k = 0; k < 9; k++) {
        float f = v[k] * invq;                      // in [-126, 126]
        int w1 = __float2int_rn(f);
        float r = f - (float)w1;
        int w2 = __float2int_rn(r * 128.0f);        // in [-64, 64]
        unsigned char* base = g_wa8 + ((size_t)(b * 9 + k) * 2) * A_T8;
        base[off] = (unsigned char)(w1 & 0xff);
        base[A_T8 + off] = (unsigned char)(w2 & 0xff);
    }
}

// ---------------- Kernel 4: IMMA int8 implicit-GEMM conv ----------------
// CTA = (px-tile, h, b): 128 oc x 64 px. 8 warps = 2(M) x 4(N). Warp: 64 oc x 16 px.
// Register budget: 64 int accs + 8 B-frags + 4 transient A-frag -> no spills at 128-reg cap.
#define DYN_SMEM (2 * B_T8)   // 16896 B
__global__ __launch_bounds__(256, 2) void k_conv(const float* __restrict__ x,
                                                 float* __restrict__ out) {
    extern __shared__ unsigned char sm[];
    unsigned char* B1 = sm;            // X1 term
    unsigned char* B2 = sm + B_T8;     // X2 term

    int px0 = blockIdx.x * 64, h = blockIdx.y, b = blockIdx.z;
    int tid = threadIdx.x, wid = tid >> 5, lane = tid & 31;
    int warp_m = wid >> 2, warp_n = wid & 3;

    int c1[4][2][4], c2[4][2][4];      // S1 = W1X1 ; S2 = W1X2 + W2X1
    #pragma unroll
    for (int mi = 0; mi < 4; mi++)
        #pragma unroll
        for (int ni = 0; ni < 2; ni++)
            #pragma unroll
            for (int r = 0; r < 4; r++) { c1[mi][ni][r] = 0; c2[mi][ni][r] = 0; }

    float tx = __uint_as_float(g_xmax_bits) * (1.0f / 126.0f);
    float inv_tx = (tx > 0.f) ? (1.0f / tx) : 0.f;

    uint32_t Bb1 = smem_u32(B1), Bb2 = smem_u32(B2);

    for (int ky = 0; ky < 3; ky++) {
        int hh = h + ky - 1;
        if ((unsigned)hh >= HV) continue;

        __syncthreads();   // previous taps done reading B
        // ---- stage B row hh: quantize to 2-term int8, IMMA-fragment packed ----
        for (int it = tid; it < 4 * NPXI; it += 256) {
            int ks = it / NPXI, pxi = it % NPXI;
            int w = px0 + pxi - 1;
            bool valid = (unsigned)w < WV;
            const float* xp = x + ((size_t)(b * CV + ks * 32) * HV + hh) * WV + (valid ? w : 0);
            uint32_t u1[8] = {0,0,0,0,0,0,0,0}, u2[8] = {0,0,0,0,0,0,0,0};
            #pragma unroll
            for (int j = 0; j < 32; j++) {
                float f = valid ? xp[(size_t)j * HV * WV] * inv_tx : 0.f;
                int i1 = __float2int_rn(f);
                float r = f - (float)i1;
                int i2 = __float2int_rn(r * 128.0f);
                int wi = (((j & 15) >> 2) << 1) | (j >> 4);
                int sh = (j & 3) * 8;
                u1[wi] |= (uint32_t)(i1 & 0xff) << sh;
                u2[wi] |= (uint32_t)(i2 & 0xff) << sh;
            }
            uint32_t boff = (uint32_t)(ks * NPXI + pxi) * 32;
            *(uint4*)(B1 + boff)      = make_uint4(u1[0], u1[1], u1[2], u1[3]);
            *(uint4*)(B1 + boff + 16) = make_uint4(u1[4], u1[5], u1[6], u1[7]);
            *(uint4*)(B2 + boff)      = make_uint4(u2[0], u2[1], u2[2], u2[3]);
            *(uint4*)(B2 + boff + 16) = make_uint4(u2[4], u2[5], u2[6], u2[7]);
        }
        __syncthreads();   // B published

        #pragma unroll
        for (int kx = 0; kx < 3; kx++) {
            const unsigned char* A1 = g_wa8 + ((size_t)(b * 9 + ky * 3 + kx) * 2) * A_T8;
            const unsigned char* A2 = A1 + A_T8;
            int pxr = warp_n * 16 + (lane >> 2) + kx;   // shifted pixel row
            #pragma unroll
            for (int ks = 0; ks < 4; ks++) {
                uint32_t b1f[2][2], b2f[2][2];
                #pragma unroll
                for (int ni = 0; ni < 2; ni++) {
                    uint32_t bo = (uint32_t)((ks * NPXI + pxr + ni * 8) * 32 + (lane & 3) * 8);
                    asm volatile("ld.shared.v2.u32 {%0,%1}, [%2];"
                                 : "=r"(b1f[ni][0]), "=r"(b1f[ni][1]) : "r"(Bb1 + bo));
                    asm volatile("ld.shared.v2.u32 {%0,%1}, [%2];"
                                 : "=r"(b2f[ni][0]), "=r"(b2f[ni][1]) : "r"(Bb2 + bo));
                }
                // pass 1: P11 into c1, P12 into c2 (A1 transient)
                #pragma unroll
                for (int mi = 0; mi < 4; mi++) {
                    uint32_t ao = (uint32_t)((ks * 8 + warp_m * 4 + mi) * 32 + lane) * 16;
                    uint4 a1v = __ldg((const uint4*)(A1 + ao));
                    uint32_t a1[4] = { a1v.x, a1v.y, a1v.z, a1v.w };
                    #pragma unroll
                    for (int ni = 0; ni < 2; ni++) {
                        imma(c1[mi][ni], a1, b1f[ni]);     // W1*X1
                        imma(c2[mi][ni], a1, b2f[ni]);     // W1*X2
                    }
                }
                // pass 2: P21 into c2 (A2 reloaded -> L1 hit; no extra live regs)
                #pragma unroll
                for (int mi = 0; mi < 4; mi++) {
                    uint32_t ao = (uint32_t)((ks * 8 + warp_m * 4 + mi) * 32 + lane) * 16;
                    uint4 a2v = __ldg((const uint4*)(A2 + ao));
                    uint32_t a2[4] = { a2v.x, a2v.y, a2v.z, a2v.w };
                    #pragma unroll
                    for (int ni = 0; ni < 2; ni++)
                        imma(c2[mi][ni], a2, b1f[ni]);     // W2*X1
                }
            }
        }
    }

    // ---- epilogue: combine terms, scale, store ----
    #pragma unroll
    for (int mi = 0; mi < 4; mi++) {
        int oc = warp_m * 64 + mi * 16 + (lane >> 2);
        float s0 = g_sw[b * CV + oc] * tx;
        float s1 = g_sw[b * CV + oc + 8] * tx;
        #pragma unroll
        for (int ni = 0; ni < 2; ni++) {
            int px = px0 + warp_n * 16 + ni * 8 + (lane & 3) * 2;
            float* op = out + ((size_t)(b * CV + oc) * HV + h) * WV + px;
            float v0 = ((float)c1[mi][ni][0] + (float)c2[mi][ni][0] * 0.0078125f) * s0;
            float v1 = ((float)c1[mi][ni][1] + (float)c2[mi][ni][1] * 0.0078125f) * s0;
            float v2 = ((float)c1[mi][ni][2] + (float)c2[mi][ni][2] * 0.0078125f) * s1;
            float v3 = ((float)c1[mi][ni][3] + (float)c2[mi][ni][3] * 0.0078125f) * s1;
            *(float2*)op = make_float2(v0, v1);
            *(float2*)(op + (size_t)8 * HV * WV) = make_float2(v2, v3);
        }
    }
}

extern "C" void kernel_launch(void* const* d_in, const int* in_sizes, int n_in,
                              void* d_out, int out_size) {
    const float* x      = (const float*)d_in[0];  // (16,128,128,128)
    const float* style  = (const float*)d_in[1];  // (16,128)
    const float* weight = (const float*)d_in[2];  // (128,128,3,3)
    float* out = (float*)d_out;                   // (16,128,128,128)

    cudaFuncSetAttribute(k_conv, cudaFuncAttributeMaxDynamicSharedMemorySize, DYN_SMEM);

    k_smax<<<16, 32>>>(style);                         // also resets g_xmax_bits
    k_xmax<<<1024, 256>>>(x, BV * CV * HV * WV);
    k_wmax<<<128, 128>>>(weight);
    k_mod<<<dim3(128, 16), 128>>>(style, weight);
    k_conv<<<dim3(2, HV, BV), 256, DYN_SMEM>>>(x, out);
}

// round 13
// speedup vs baseline: 7.3812x; 7.3812x over previous
#include <cuda_runtime.h>
#include <cuda_fp16.h>
#include <stdint.h>
#include <math.h>

#define BV 16
#define CV 128
#define HV 128
#define WV 128

#define A_TILE 32768           // packed A: [kstep 8][mtile 8][lane 32][16B] fp16
#define B_TILE 34816           // packed B: [kstep 8][pxi 136][32B] fp16
#define NPX 136                // pixel rows incl. halo (pxi = w+1, w in [-1,134])

__device__ float g_smax[BV];
__device__ float g_wmax[CV];
// Pre-packed fp16 A tiles: [b][tap 0..8], each 32KB, HMMA-fragment packed
__device__ unsigned char g_wa[(size_t)BV * 9 * A_TILE];

// ---------------- helpers ----------------
__device__ __forceinline__ uint32_t smem_u32(const void* p) {
    uint32_t a;
    asm("{ .reg .u64 t; cvta.to.shared.u64 t, %1; cvt.u32.u64 %0, t; }" : "=r"(a) : "l"(p));
    return a;
}
// A fragment packing (mma.m16n8k16 A frag, row-major M x K)
__device__ __forceinline__ uint32_t addrA(int o, int ic) {
    int kstep = ic >> 4, kk = ic & 15, mt = o >> 4;
    int lane = ((o & 7) << 2) | ((kk & 7) >> 1);
    int reg = ((kk >> 3) << 1) | ((o >> 3) & 1);
    return (uint32_t)(((kstep * 8 + mt) * 32 + lane) * 16 + reg * 4 + (kk & 1) * 2);
}

__device__ __forceinline__ void mma_f16(float* c, const uint32_t* a, const uint32_t* b2) {
    asm volatile(
        "mma.sync.aligned.m16n8k16.row.col.f32.f16.f16.f32 "
        "{%0,%1,%2,%3}, {%4,%5,%6,%7}, {%8,%9}, {%0,%1,%2,%3};"
        : "+f"(c[0]), "+f"(c[1]), "+f"(c[2]), "+f"(c[3])
        : "r"(a[0]), "r"(a[1]), "r"(a[2]), "r"(a[3]), "r"(b2[0]), "r"(b2[1]));
}

// ---------------- Kernel 1: per-sample style inf-norm ----------------
__global__ void k_smax(const float* __restrict__ style) {
    int b = blockIdx.x, t = threadIdx.x;
    float m = 0.f;
    for (int i = t; i < CV; i += 32) m = fmaxf(m, fabsf(style[b * CV + i]));
    #pragma unroll
    for (int o = 16; o; o >>= 1) m = fmaxf(m, __shfl_xor_sync(0xffffffffu, m, o));
    if (t == 0) g_smax[b] = m;
}

// ---------------- Kernel 2: per-out-channel weight inf-norm ----------------
__global__ void k_wmax(const float* __restrict__ weight) {
    int o = blockIdx.x, t = threadIdx.x;
    const float* wp = weight + (size_t)o * CV * 9;
    float m = 0.f;
    for (int i = t; i < CV * 9; i += 128) m = fmaxf(m, fabsf(wp[i]));
    __shared__ float red[4];
    #pragma unroll
    for (int off = 16; off; off >>= 1) m = fmaxf(m, __shfl_xor_sync(0xffffffffu, m, off));
    if ((t & 31) == 0) red[t >> 5] = m;
    __syncthreads();
    if (t == 0) g_wmax[o] = fmaxf(fmaxf(red[0], red[1]), fmaxf(red[2], red[3]));
}

// ---------------- Kernel 3: modulate+demodulate -> packed fp16 A tiles ----------------
__global__ void k_mod(const float* __restrict__ style, const float* __restrict__ weight) {
    int o = blockIdx.x, b = blockIdx.y, i = threadIdx.x;
    float s = style[b * CV + i] / g_smax[b];
    float scale = (1.0f / sqrtf((float)(CV * 9))) / g_wmax[o] * s;
    const float* wp = weight + ((size_t)o * CV + i) * 9;
    float v[9];
    float ss = 0.f;
    #pragma unroll
    for (int k = 0; k < 9; k++) { v[k] = wp[k] * scale; ss += v[k] * v[k]; }
    __shared__ float red[4];
    #pragma unroll
    for (int off = 16; off; off >>= 1) ss += __shfl_xor_sync(0xffffffffu, ss, off);
    if ((i & 31) == 0) red[i >> 5] = ss;
    __syncthreads();
    float coe = rsqrtf(red[0] + red[1] + red[2] + red[3] + 1e-8f);
    uint32_t off = addrA(o, i);
    #pragma unroll
    for (int k = 0; k < 9; k++) {
        __half hv = __float2half_rn(v[k] * coe);
        unsigned char* base = g_wa + (size_t)(b * 9 + k) * A_TILE;   // tap = ky*3+kx
        *(unsigned short*)(base + off) = __half_as_ushort(hv);
    }
}

// ---------------- Kernel 4: fp16 HMMA implicit-GEMM conv ----------------
// CTA = (h, b). 8 warps = 2(M) x 4(N). Warp: 64 oc x 32 px.
// A fragments straight from g_wa via LDG (L1-resident, shared with co-resident CTA).
#define DYN_SMEM (B_TILE)   // 34816 B
__global__ __launch_bounds__(256, 2) void k_conv(const float* __restrict__ x,
                                                 float* __restrict__ out) {
    extern __shared__ unsigned char sm[];
    unsigned char* Bs = sm;

    int h = blockIdx.x, b = blockIdx.y;
    int tid = threadIdx.x, wid = tid >> 5, lane = tid & 31;
    int warp_m = wid >> 2, warp_n = wid & 3;

    float c[4][4][4];
    #pragma unroll
    for (int mi = 0; mi < 4; mi++)
        #pragma unroll
        for (int ni = 0; ni < 4; ni++)
            #pragma unroll
            for (int r = 0; r < 4; r++) c[mi][ni][r] = 0.f;

    uint32_t Bbase = smem_u32(Bs);

    for (int ky = 0; ky < 3; ky++) {
        int hh = h + ky - 1;
        if ((unsigned)hh >= HV) continue;

        __syncthreads();   // previous taps done reading B
        // ---- stage B row hh: per (kstep, pxi) one contiguous 32B block
        // ushort order within block: 0,1,8,9, 2,3,10,11, 4,5,12,13, 6,7,14,15
        {
            const float* xrow = x + ((size_t)(b * CV) * HV + hh) * WV;
            for (int it = tid; it < 8 * NPX; it += 256) {
                int ks = it / NPX, pxi = it % NPX;
                int w = pxi - 1;
                bool valid = (unsigned)w < WV;
                const float* xp = xrow + (size_t)(ks * 16) * HV * WV + (valid ? w : 0);
                unsigned short hs[16];
                #pragma unroll
                for (int j = 0; j < 16; j++) {
                    float f = valid ? xp[(size_t)j * HV * WV] : 0.f;
                    int pos = (((j & 7) >> 1) << 2) | ((j >> 3) << 1) | (j & 1);
                    hs[pos] = __half_as_ushort(__float2half_rn(f));
                }
                uint32_t boff = (uint32_t)(ks * NPX + pxi) * 32;
                *(uint4*)(Bs + boff)      = *(uint4*)&hs[0];
                *(uint4*)(Bs + boff + 16) = *(uint4*)&hs[8];
            }
        }
        __syncthreads();   // B published

        #pragma unroll
        for (int kx = 0; kx < 3; kx++) {
            const unsigned char* Ah = g_wa + (size_t)(b * 9 + ky * 3 + kx) * A_TILE;
            int pxr = warp_n * 32 + (lane >> 2) + kx;   // shifted pixel row
            #pragma unroll
            for (int ks = 0; ks < 8; ks++) {
                uint32_t bf[4][2];
                #pragma unroll
                for (int ni = 0; ni < 4; ni++) {
                    uint32_t bo = (uint32_t)((ks * NPX + pxr + ni * 8) * 4 + (lane & 3)) * 8;
                    asm volatile("ld.shared.v2.u32 {%0,%1}, [%2];"
                                 : "=r"(bf[ni][0]), "=r"(bf[ni][1]) : "r"(Bbase + bo));
                }
                #pragma unroll
                for (int mi = 0; mi < 4; mi++) {
                    uint32_t ao = (uint32_t)((ks * 8 + warp_m * 4 + mi) * 32 + lane) * 16;
                    uint4 av = __ldg((const uint4*)(Ah + ao));
                    uint32_t af[4] = { av.x, av.y, av.z, av.w };
                    #pragma unroll
                    for (int ni = 0; ni < 4; ni++)
                        mma_f16(c[mi][ni], af, bf[ni]);
                }
            }
        }
    }

    // ---- epilogue: C regs -> out, 8B stores ----
    #pragma unroll
    for (int mi = 0; mi < 4; mi++) {
        #pragma unroll
        for (int ni = 0; ni < 4; ni++) {
            int oc = warp_m * 64 + mi * 16 + (lane >> 2);
            int px = warp_n * 32 + ni * 8 + (lane & 3) * 2;
            float* op = out + ((size_t)(b * CV + oc) * HV + h) * WV + px;
            *(float2*)op = make_float2(c[mi][ni][0], c[mi][ni][1]);
            *(float2*)(op + (size_t)8 * HV * WV) = make_float2(c[mi][ni][2], c[mi][ni][3]);
        }
    }
}

extern "C" void kernel_launch(void* const* d_in, const int* in_sizes, int n_in,
                              void* d_out, int out_size) {
    const float* x      = (const float*)d_in[0];  // (16,128,128,128)
    const float* style  = (const float*)d_in[1];  // (16,128)
    const float* weight = (const float*)d_in[2];  // (128,128,3,3)
    float* out = (float*)d_out;                   // (16,128,128,128)

    cudaFuncSetAttribute(k_conv, cudaFuncAttributeMaxDynamicSharedMemorySize, DYN_SMEM);

    k_smax<<<16, 32>>>(style);
    k_wmax<<<128, 128>>>(weight);
    k_mod<<<dim3(128, 16), 128>>>(style, weight);
    k_conv<<<dim3(HV, BV), 256, DYN_SMEM>>>(x, out);
}